// round 5
// baseline (speedup 1.0000x reference)
#include <cuda_runtime.h>
#include <cstdint>
#include <cstddef>

#define BB 512
#define TT 1024
#define II 64
#define HH 10
#define GG 40

typedef unsigned long long ull;

// Scratch: gate pre-activations (pre-scaled: 0.5x for sigmoid rows i/f/o,
// 1.0x for tanh rows g). Static device arrays (no allocs allowed).
__device__ float g_xg1[(size_t)BB * TT * GG];
__device__ float g_xg2[(size_t)BB * TT * GG];

// ---------------------------------------------------------------------------
// f32x2 packed helpers (Blackwell FFMA2 path — only reachable via PTX)
// ---------------------------------------------------------------------------
__device__ __forceinline__ ull ffma2(ull a, ull b, ull c)
{
    ull d;
    asm("fma.rn.f32x2 %0, %1, %2, %3;" : "=l"(d) : "l"(a), "l"(b), "l"(c));
    return d;
}
__device__ __forceinline__ ull pack2(float x)
{
    ull d;
    asm("mov.b64 %0, {%1, %1};" : "=l"(d) : "f"(x));
    return d;
}
__device__ __forceinline__ ull pk(float lo, float hi)
{
    ull d;
    asm("mov.b64 %0, {%1, %2};" : "=l"(d) : "f"(lo), "f"(hi));
    return d;
}
__device__ __forceinline__ float hsum(ull d)
{
    float lo, hi;
    asm("mov.b64 {%0, %1}, %2;" : "=f"(lo), "=f"(hi) : "l"(d));
    return lo + hi;
}
__device__ __forceinline__ float tanh_ap(float x)
{
    float y;
    asm("tanh.approx.f32 %0, %1;" : "=f"(y) : "f"(x));
    return y;
}

// ---------------------------------------------------------------------------
// Kernel 1: xg1[r,g] = scale(g)*(b[g] + sum_d x[r,d]*Wih1[g,d]), r=(b,t).
// 4 rows x 20 gates per thread: 5 LDS.128 feed 40 ffma2 per k-slice.
// ---------------------------------------------------------------------------
__global__ void __launch_bounds__(256) xg1_kernel(
    const float* __restrict__ x,
    const float* __restrict__ Wih1,
    const float* __restrict__ bih1,
    const float* __restrict__ bhh1)
{
    __shared__ __align__(16) float Wt[II * GG];   // Wt[d*GG + g], prescaled
    __shared__ __align__(16) float bs[GG];
    int tid = threadIdx.x;
    for (int i = tid; i < II * GG; i += 256) {
        int d = i / GG, g = i % GG;
        float s = (g >= 20 && g < 30) ? 1.0f : 0.5f;
        Wt[i] = Wih1[g * II + d] * s;
    }
    if (tid < GG) {
        float s = (tid >= 20 && tid < 30) ? 1.0f : 0.5f;
        bs[tid] = (bih1[tid] + bhh1[tid]) * s;
    }
    __syncthreads();

    int half = tid >> 7;                 // gate half: 0 -> gates 0..19, 1 -> 20..39
    int rq = tid & 127;
    size_t rbase = (size_t)blockIdx.x * 512 + rq;   // rows rbase + 128*m

    const float4* xr[4];
#pragma unroll
    for (int m = 0; m < 4; m++) xr[m] = (const float4*)(x + (rbase + 128 * m) * II);

    ull acc[4][10];
    const ull* bsp = (const ull*)bs;     // 20 bias pairs
#pragma unroll
    for (int m = 0; m < 4; m++)
#pragma unroll
        for (int p = 0; p < 10; p++) acc[m][p] = bsp[half * 10 + p];

#pragma unroll 2
    for (int d4 = 0; d4 < II / 4; d4++) {
        float4 xv[4];
#pragma unroll
        for (int m = 0; m < 4; m++) xv[m] = xr[m][d4];
#pragma unroll
        for (int k = 0; k < 4; k++) {
            ull xp[4];
#pragma unroll
            for (int m = 0; m < 4; m++) {
                float f = (k == 0) ? xv[m].x : (k == 1) ? xv[m].y
                        : (k == 2) ? xv[m].z : xv[m].w;
                xp[m] = pack2(f);
            }
            const ulonglong2* wr =
                (const ulonglong2*)(Wt + (d4 * 4 + k) * GG + half * 20);
#pragma unroll
            for (int p2 = 0; p2 < 5; p2++) {       // 5 LDS.128 -> 40 ffma2
                ulonglong2 w = wr[p2];
#pragma unroll
                for (int m = 0; m < 4; m++) {
                    acc[m][p2 * 2 + 0] = ffma2(xp[m], w.x, acc[m][p2 * 2 + 0]);
                    acc[m][p2 * 2 + 1] = ffma2(xp[m], w.y, acc[m][p2 * 2 + 1]);
                }
            }
        }
    }

#pragma unroll
    for (int m = 0; m < 4; m++) {
        ulonglong2* o = (ulonglong2*)(g_xg1 + (rbase + 128 * m) * GG + half * 20);
#pragma unroll
        for (int p2 = 0; p2 < 5; p2++)
            o[p2] = make_ulonglong2(acc[m][p2 * 2], acc[m][p2 * 2 + 1]);
    }
}

// ---------------------------------------------------------------------------
// One LSTM cell step (packed-f32x2 dots, MUFU.TANH activations).
// hp[5]: packed replicated hidden state. Returns this lane's hn (lane j < 10
// holds h_j). Updates hp and cown in place.
// ---------------------------------------------------------------------------
__device__ __forceinline__ float lstm_step(
    ull hp[5], float& cown, float pre0, float pre1,
    const ull wa[5], const ull wb[5], bool isg, int L)
{
    ull acc0 = pk(pre0, 0.0f);
    ull acc1 = pk(pre1, 0.0f);
#pragma unroll
    for (int j = 0; j < 5; j++) {
        acc0 = ffma2(hp[j], wa[j], acc0);
        acc1 = ffma2(hp[j], wb[j], acc1);
    }
    float a0 = hsum(acc0), a1 = hsum(acc1);
    float t0 = tanh_ap(a0), t1 = tanh_ap(a1);
    float act0 = fmaf(t0, 0.5f, 0.5f);                 // sigmoid(i/f)
    float act1 = isg ? t1 : fmaf(t1, 0.5f, 0.5f);      // tanh(g) / sigmoid(o)
    float sf = __shfl_sync(0xffffffffu, act0, L + 10); // sigmoid(f_j)
    float so = __shfl_sync(0xffffffffu, act1, L + 10); // sigmoid(o_j)
    float cn = fmaf(sf, cown, act0 * act1);
    float tc = tanh_ap(cn);
    float hn = so * tc;
    if (L < 10) cown = cn;
    float h[10];
#pragma unroll
    for (int j = 0; j < 10; j++) h[j] = __shfl_sync(0xffffffffu, hn, j);
#pragma unroll
    for (int j = 0; j < 5; j++) hp[j] = pk(h[2 * j], h[2 * j + 1]);
    return hn;
}

__device__ __forceinline__ float dotb(const ull hp[5], const ull w[5], ull b)
{
    ull acc = b;
#pragma unroll
    for (int j = 0; j < 5; j++) acc = ffma2(hp[j], w[j], acc);
    return hsum(acc);
}

// ---------------------------------------------------------------------------
// Kernel 2: warp handles TWO batch chains (ILP fills latency stalls; weights
// shared). layer1 -> xg2 on the fly -> layer2 -> fused fc1/fc2 epilogue.
// ---------------------------------------------------------------------------
__global__ void __launch_bounds__(128) scan_kernel(
    const float* __restrict__ h0,   const float* __restrict__ c0,
    const float* __restrict__ Whh1, const float* __restrict__ Wih2,
    const float* __restrict__ Whh2, const float* __restrict__ bih2,
    const float* __restrict__ bhh2, const float* __restrict__ fc1w,
    const float* __restrict__ fc1b, const float* __restrict__ fc2w,
    const float* __restrict__ fc2b, float* __restrict__ out)
{
    const int warp = threadIdx.x >> 5;
    const int lane = threadIdx.x & 31;
    const int bp = (blockIdx.x * 4 + warp) * 2;    // batches bp, bp+1 (grid=64)
    const int L = lane;
    const int row0 = (L < 20) ? L : 0;
    const int row1 = row0 + 20;
    const bool isg = (L < 10);
    const float s0 = 0.5f;
    const float s1 = isg ? 1.0f : 0.5f;

    ull w1a[5], w1b[5], w2a[5], w2b[5], wi2a[5], wi2b[5];
#pragma unroll
    for (int j = 0; j < 5; j++) {
        w1a[j]  = pk(Whh1[row0 * HH + 2 * j] * s0, Whh1[row0 * HH + 2 * j + 1] * s0);
        w1b[j]  = pk(Whh1[row1 * HH + 2 * j] * s1, Whh1[row1 * HH + 2 * j + 1] * s1);
        w2a[j]  = pk(Whh2[row0 * HH + 2 * j] * s0, Whh2[row0 * HH + 2 * j + 1] * s0);
        w2b[j]  = pk(Whh2[row1 * HH + 2 * j] * s1, Whh2[row1 * HH + 2 * j + 1] * s1);
        wi2a[j] = pk(Wih2[row0 * HH + 2 * j] * s0, Wih2[row0 * HH + 2 * j + 1] * s0);
        wi2b[j] = pk(Wih2[row1 * HH + 2 * j] * s1, Wih2[row1 * HH + 2 * j + 1] * s1);
    }
    const ull b2a = pk((bih2[row0] + bhh2[row0]) * s0, 0.0f);
    const ull b2b = pk((bih2[row1] + bhh2[row1]) * s1, 0.0f);

    ull hpA[5], hpB[5];
#pragma unroll
    for (int j = 0; j < 5; j++) {
        hpA[j] = pk(h0[bp * HH + 2 * j],       h0[bp * HH + 2 * j + 1]);
        hpB[j] = pk(h0[(bp + 1) * HH + 2 * j], h0[(bp + 1) * HH + 2 * j + 1]);
    }
    float cA = (L < HH) ? c0[bp * HH + L] : 0.0f;
    float cB = (L < HH) ? c0[(bp + 1) * HH + L] : 0.0f;

    const float* x1A = g_xg1 + (size_t)bp * TT * GG;
    const float* x1B = g_xg1 + (size_t)(bp + 1) * TT * GG;
    float*       x2A = g_xg2 + (size_t)bp * TT * GG;
    float*       x2B = g_xg2 + (size_t)(bp + 1) * TT * GG;

    float bA0[8], bA1[8], bB0[8], bB1[8];
#pragma unroll
    for (int k = 0; k < 8; k++) {
        bA0[k] = x1A[k * GG + row0];  bA1[k] = x1A[k * GG + row1];
        bB0[k] = x1B[k * GG + row0];  bB1[k] = x1B[k * GG + row1];
    }

    // ---- layer 1 (both chains) ----
    for (int t0 = 0; t0 < TT; t0 += 8) {
#pragma unroll
        for (int s = 0; s < 8; s++) {
            int t = t0 + s, tp = t + 8;            // prefetch depth 8
            float pa0 = bA0[s], pa1 = bA1[s], pb0 = bB0[s], pb1 = bB1[s];
            if (tp < TT) {
                bA0[s] = x1A[tp * GG + row0];  bA1[s] = x1A[tp * GG + row1];
                bB0[s] = x1B[tp * GG + row0];  bB1[s] = x1B[tp * GG + row1];
            }
            lstm_step(hpA, cA, pa0, pa1, w1a, w1b, isg, L);
            lstm_step(hpB, cB, pb0, pb1, w1a, w1b, isg, L);
            float xa0 = dotb(hpA, wi2a, b2a), xa1 = dotb(hpA, wi2b, b2b);
            float xb0 = dotb(hpB, wi2a, b2a), xb1 = dotb(hpB, wi2b, b2b);
            if (L < 20) {
                x2A[t * GG + row0] = xa0;  x2A[t * GG + row1] = xa1;
                x2B[t * GG + row0] = xb0;  x2B[t * GG + row1] = xb1;
            }
        }
    }

    __threadfence_block();   // xg2 stores visible across lanes of this warp
    __syncwarp();

    // ---- layer 2 (init state = layer-1 final state) ----
    float AA = 0.0f, AB = 0.0f, sumw = 0.0f;
    float wbuf[8];
#pragma unroll
    for (int k = 0; k < 8; k++) {
        bA0[k] = x2A[k * GG + row0];  bA1[k] = x2A[k * GG + row1];
        bB0[k] = x2B[k * GG + row0];  bB1[k] = x2B[k * GG + row1];
        wbuf[k] = fc2w[k];
    }
    for (int t0 = 0; t0 < TT; t0 += 8) {
#pragma unroll
        for (int s = 0; s < 8; s++) {
            int t = t0 + s, tp = t + 8;
            float pa0 = bA0[s], pa1 = bA1[s], pb0 = bB0[s], pb1 = bB1[s];
            float wt = wbuf[s];
            if (tp < TT) {
                bA0[s] = x2A[tp * GG + row0];  bA1[s] = x2A[tp * GG + row1];
                bB0[s] = x2B[tp * GG + row0];  bB1[s] = x2B[tp * GG + row1];
                wbuf[s] = fc2w[tp];
            }
            float hA = lstm_step(hpA, cA, pa0, pa1, w2a, w2b, isg, L);
            float hB = lstm_step(hpB, cB, pb0, pb1, w2a, w2b, isg, L);
            sumw += wt;
            AA = fmaf(wt, hA, AA);     // lane j: sum_t fc2w[t]*h2_j(t)
            AB = fmaf(wt, hB, AB);
        }
    }

    // ---- fused fc1/fc2 epilogue (both chains) ----
    float pa = (L < 10) ? AA * fc1w[L] : 0.0f;
    float pb = (L < 10) ? AB * fc1w[L] : 0.0f;
#pragma unroll
    for (int off = 16; off; off >>= 1) {
        pa += __shfl_xor_sync(0xffffffffu, pa, off);
        pb += __shfl_xor_sync(0xffffffffu, pb, off);
    }
    if (lane == 0) {
        out[bp]     = pa + fc1b[0] * sumw + fc2b[0];
        out[bp + 1] = pb + fc1b[0] * sumw + fc2b[0];
    }
}

// ---------------------------------------------------------------------------
// Inputs (metadata order): x, h0, c0, Wih1, Whh1, bih1, bhh1, Wih2, Whh2,
//                          bih2, bhh2, fc1_w, fc1_b, fc2_w, fc2_b
// ---------------------------------------------------------------------------
extern "C" void kernel_launch(void* const* d_in, const int* in_sizes, int n_in,
                              void* d_out, int out_size)
{
    const float* x     = (const float*)d_in[0];
    const float* h0    = (const float*)d_in[1];
    const float* c0    = (const float*)d_in[2];
    const float* Wih1  = (const float*)d_in[3];
    const float* Whh1  = (const float*)d_in[4];
    const float* bih1  = (const float*)d_in[5];
    const float* bhh1  = (const float*)d_in[6];
    const float* Wih2  = (const float*)d_in[7];
    const float* Whh2  = (const float*)d_in[8];
    const float* bih2  = (const float*)d_in[9];
    const float* bhh2  = (const float*)d_in[10];
    const float* fc1w  = (const float*)d_in[11];
    const float* fc1b  = (const float*)d_in[12];
    const float* fc2w  = (const float*)d_in[13];
    const float* fc2b  = (const float*)d_in[14];
    float* out = (float*)d_out;

    xg1_kernel<<<(BB * TT) / 512, 256>>>(x, Wih1, bih1, bhh1);
    scan_kernel<<<BB / 8, 128>>>(h0, c0, Whh1, Wih2, Whh2, bih2, bhh2,
                                 fc1w, fc1b, fc2w, fc2b, out);
}

// round 8
// speedup vs baseline: 1.0567x; 1.0567x over previous
#include <cuda_runtime.h>
#include <cstdint>
#include <cstddef>

#define BB 512
#define TT 1024
#define II 64
#define HH 10
#define GG 40

typedef unsigned long long ull;

// Scratch (static device arrays; no allocs allowed).
// g_xg1 / g_xg2 hold gate pre-activations in PAIR-INTERLEAVED layout:
//   word[2L] = gate L, word[2L+1] = gate L+20   (L = 0..19)
// pre-scaled: 0.5x for sigmoid rows (i/f/o), 1.0x for tanh rows (g).
__device__ float g_xg1[(size_t)BB * TT * GG];
__device__ float g_xg2[(size_t)BB * TT * GG];
__device__ float g_h1[(size_t)BB * TT * HH];   // layer-1 hidden states
__device__ float g_c1[BB * HH];                // layer-1 final cell state

// ---------------------------------------------------------------------------
// helpers
// ---------------------------------------------------------------------------
__device__ __forceinline__ ull ffma2(ull a, ull b, ull c)
{
    ull d;
    asm("fma.rn.f32x2 %0, %1, %2, %3;" : "=l"(d) : "l"(a), "l"(b), "l"(c));
    return d;
}
__device__ __forceinline__ ull pack2(float x)
{
    ull d;
    asm("mov.b64 %0, {%1, %1};" : "=l"(d) : "f"(x));
    return d;
}
__device__ __forceinline__ float tanh_ap(float x)
{
    float y;
    asm("tanh.approx.f32 %0, %1;" : "=f"(y) : "f"(x));
    return y;
}
__device__ __forceinline__ float ulo(ull v) { float2 f = *(float2*)&v; return f.x; }
__device__ __forceinline__ float uhi(ull v) { float2 f = *(float2*)&v; return f.y; }

// ---------------------------------------------------------------------------
// Kernel 1: xg1 GEMM.  1 row x 40 gates per thread (20 packed accs, 40 regs).
// Stores pair-interleaved layout.
// ---------------------------------------------------------------------------
__global__ void __launch_bounds__(512) xg1_kernel(
    const float* __restrict__ x,
    const float* __restrict__ Wih1,
    const float* __restrict__ bih1,
    const float* __restrict__ bhh1)
{
    __shared__ __align__(16) float Wt[II * GG];   // Wt[d*GG + g], prescaled
    __shared__ __align__(16) float bs[GG];
    int tid = threadIdx.x;
    for (int i = tid; i < II * GG; i += 512) {
        int d = i / GG, g = i % GG;
        float s = (g >= 20 && g < 30) ? 1.0f : 0.5f;
        Wt[i] = Wih1[g * II + d] * s;
    }
    if (tid < GG) {
        float s = (tid >= 20 && tid < 30) ? 1.0f : 0.5f;
        bs[tid] = (bih1[tid] + bhh1[tid]) * s;
    }
    __syncthreads();

    size_t row = (size_t)blockIdx.x * 512 + tid;      // 1024 blocks cover 524288
    const float4* xr = (const float4*)(x + row * II);

    ull acc[20];                                      // acc[p] = gates (2p, 2p+1)
    const ull* bsp = (const ull*)bs;
#pragma unroll
    for (int p = 0; p < 20; p++) acc[p] = bsp[p];

#pragma unroll 4
    for (int d4 = 0; d4 < II / 4; d4++) {
        float4 xv = xr[d4];
#pragma unroll
        for (int k = 0; k < 4; k++) {
            float f = (k == 0) ? xv.x : (k == 1) ? xv.y : (k == 2) ? xv.z : xv.w;
            ull xp = pack2(f);
            const ulonglong2* wr = (const ulonglong2*)(Wt + (d4 * 4 + k) * GG);
#pragma unroll
            for (int p2 = 0; p2 < 10; p2++) {
                ulonglong2 w = wr[p2];
                acc[p2 * 2 + 0] = ffma2(xp, w.x, acc[p2 * 2 + 0]);
                acc[p2 * 2 + 1] = ffma2(xp, w.y, acc[p2 * 2 + 1]);
            }
        }
    }

    // pair-interleave store: word 4q.. = (g_{2q}, g_{2q+20}, g_{2q+1}, g_{2q+21})
    float4* o = (float4*)(g_xg1 + row * GG);
#pragma unroll
    for (int q = 0; q < 10; q++)
        o[q] = make_float4(ulo(acc[q]), ulo(acc[q + 10]),
                           uhi(acc[q]), uhi(acc[q + 10]));
}

// ---------------------------------------------------------------------------
// Kernel 3: xg2 GEMM from stored h1.  1 row x 40 gates per thread, K=10.
// ---------------------------------------------------------------------------
__global__ void __launch_bounds__(512) xg2_kernel(
    const float* __restrict__ Wih2,
    const float* __restrict__ bih2,
    const float* __restrict__ bhh2)
{
    __shared__ __align__(16) float Wt[HH * GG];   // Wt[d*GG + g], prescaled
    __shared__ __align__(16) float bs[GG];
    int tid = threadIdx.x;
    for (int i = tid; i < HH * GG; i += 512) {
        int d = i / GG, g = i % GG;
        float s = (g >= 20 && g < 30) ? 1.0f : 0.5f;
        Wt[i] = Wih2[g * HH + d] * s;
    }
    if (tid < GG) {
        float s = (tid >= 20 && tid < 30) ? 1.0f : 0.5f;
        bs[tid] = (bih2[tid] + bhh2[tid]) * s;
    }
    __syncthreads();

    size_t row = (size_t)blockIdx.x * 512 + tid;
    const float2* hr = (const float2*)(g_h1 + row * HH);   // 5 x 8B, aligned

    ull acc[20];
    const ull* bsp = (const ull*)bs;
#pragma unroll
    for (int p = 0; p < 20; p++) acc[p] = bsp[p];

    float2 hv[5];
#pragma unroll
    for (int p = 0; p < 5; p++) hv[p] = hr[p];

#pragma unroll
    for (int d = 0; d < HH; d++) {
        float f = (d & 1) ? hv[d >> 1].y : hv[d >> 1].x;
        ull xp = pack2(f);
        const ulonglong2* wr = (const ulonglong2*)(Wt + d * GG);
#pragma unroll
        for (int p2 = 0; p2 < 10; p2++) {
            ulonglong2 w = wr[p2];
            acc[p2 * 2 + 0] = ffma2(xp, w.x, acc[p2 * 2 + 0]);
            acc[p2 * 2 + 1] = ffma2(xp, w.y, acc[p2 * 2 + 1]);
        }
    }

    float4* o = (float4*)(g_xg2 + row * GG);
#pragma unroll
    for (int q = 0; q < 10; q++)
        o[q] = make_float4(ulo(acc[q]), ulo(acc[q + 10]),
                           uhi(acc[q]), uhi(acc[q + 10]));
}

// ---------------------------------------------------------------------------
// One LSTM cell step. Scalar two-chain dots; MUFU.TANH activations.
// Lane L (<20) owns gate rows L (i/f) and L+20 (g/o); c_j owned by lane j.
// ---------------------------------------------------------------------------
__device__ __forceinline__ float cell(
    float (&h)[HH], float& cown, float pre0, float pre1,
    const float (&wa)[HH], const float (&wb)[HH], bool isg, int L)
{
    float p0 = pre0, q0 = 0.f, p1 = pre1, q1 = 0.f;
#pragma unroll
    for (int j = 0; j < 5; j++) {
        p0 = fmaf(h[j],     wa[j],     p0);
        q0 = fmaf(h[5 + j], wa[5 + j], q0);
        p1 = fmaf(h[j],     wb[j],     p1);
        q1 = fmaf(h[5 + j], wb[5 + j], q1);
    }
    float a0 = p0 + q0, a1 = p1 + q1;
    float t0 = tanh_ap(a0), t1 = tanh_ap(a1);
    float act0 = fmaf(t0, 0.5f, 0.5f);                 // sigmoid(i/f)
    float act1 = isg ? t1 : fmaf(t1, 0.5f, 0.5f);      // tanh(g) / sigmoid(o)
    float sf = __shfl_sync(0xffffffffu, act0, L + 10); // sigmoid(f_j)
    float so = __shfl_sync(0xffffffffu, act1, L + 10); // sigmoid(o_j)
    float cn = fmaf(sf, cown, act0 * act1);
    float tc = tanh_ap(cn);
    float hn = so * tc;
    if (L < 10) cown = cn;
#pragma unroll
    for (int j = 0; j < HH; j++) h[j] = __shfl_sync(0xffffffffu, hn, j);
    return hn;
}

// ---------------------------------------------------------------------------
// Kernel 2: layer-1 scan. Reads pair-layout xg1, stores h1 + final c1.
// ---------------------------------------------------------------------------
__global__ void __launch_bounds__(128) scan1_kernel(
    const float* __restrict__ h0, const float* __restrict__ c0,
    const float* __restrict__ Whh1)
{
    const int warp = threadIdx.x >> 5;
    const int lane = threadIdx.x & 31;
    const int b = blockIdx.x * 4 + warp;               // 128 blocks x 4 warps
    const int L = lane;
    const int row0 = (L < 20) ? L : 0;
    const int row1 = row0 + 20;
    const bool isg = (L < 10);
    const float s0 = 0.5f;
    const float s1 = isg ? 1.0f : 0.5f;

    float wa[HH], wb[HH];
#pragma unroll
    for (int j = 0; j < HH; j++) {
        wa[j] = Whh1[row0 * HH + j] * s0;
        wb[j] = Whh1[row1 * HH + j] * s1;
    }

    float h[HH], cown;
#pragma unroll
    for (int j = 0; j < HH; j++) h[j] = h0[b * HH + j];
    cown = (L < HH) ? c0[b * HH + L] : 0.0f;

    const float2* xp = (const float2*)(g_xg1 + (size_t)b * TT * GG);
    float* h1p = g_h1 + (size_t)b * TT * HH;

    float2 buf[8];
#pragma unroll
    for (int k = 0; k < 8; k++) buf[k] = xp[k * 20 + row0];

    for (int t0 = 0; t0 < TT; t0 += 8) {
#pragma unroll
        for (int s = 0; s < 8; s++) {
            int t = t0 + s, tp = t + 8;
            float2 pre = buf[s];
            if (tp < TT) buf[s] = xp[tp * 20 + row0];
            float hn = cell(h, cown, pre.x, pre.y, wa, wb, isg, L);
            if (L < HH) h1p[t * HH + L] = hn;
        }
    }
    if (L < HH) g_c1[b * HH + L] = cown;
}

// ---------------------------------------------------------------------------
// Kernel 4: layer-2 scan + fused fc1/fc2 epilogue.
// Init state = layer-1 final state (h1[T-1], c1).
// ---------------------------------------------------------------------------
__global__ void __launch_bounds__(128) scan2_kernel(
    const float* __restrict__ Whh2, const float* __restrict__ fc1w,
    const float* __restrict__ fc1b, const float* __restrict__ fc2w,
    const float* __restrict__ fc2b, float* __restrict__ out)
{
    const int warp = threadIdx.x >> 5;
    const int lane = threadIdx.x & 31;
    const int b = blockIdx.x * 4 + warp;
    const int L = lane;
    const int row0 = (L < 20) ? L : 0;
    const int row1 = row0 + 20;
    const bool isg = (L < 10);
    const float s0 = 0.5f;
    const float s1 = isg ? 1.0f : 0.5f;

    float wa[HH], wb[HH];
#pragma unroll
    for (int j = 0; j < HH; j++) {
        wa[j] = Whh2[row0 * HH + j] * s0;
        wb[j] = Whh2[row1 * HH + j] * s1;
    }

    float h[HH], cown;
    const float* hfin = g_h1 + (size_t)b * TT * HH + (TT - 1) * HH;
#pragma unroll
    for (int j = 0; j < HH; j++) h[j] = hfin[j];
    cown = (L < HH) ? g_c1[b * HH + L] : 0.0f;

    const float2* xp = (const float2*)(g_xg2 + (size_t)b * TT * GG);

    float2 buf[8];
    float wbuf[8];
#pragma unroll
    for (int k = 0; k < 8; k++) {
        buf[k] = xp[k * 20 + row0];
        wbuf[k] = fc2w[k];
    }

    float A = 0.0f, sumw = 0.0f;
    for (int t0 = 0; t0 < TT; t0 += 8) {
#pragma unroll
        for (int s = 0; s < 8; s++) {
            int t = t0 + s, tp = t + 8;
            float2 pre = buf[s];
            float wt = wbuf[s];
            if (tp < TT) {
                buf[s] = xp[tp * 20 + row0];
                wbuf[s] = fc2w[tp];
            }
            float hn = cell(h, cown, pre.x, pre.y, wa, wb, isg, L);
            sumw += wt;
            A = fmaf(wt, hn, A);       // lane j: sum_t fc2w[t]*h2_j(t)
        }
    }

    float part = (L < HH) ? A * fc1w[L] : 0.0f;
#pragma unroll
    for (int off = 16; off; off >>= 1)
        part += __shfl_xor_sync(0xffffffffu, part, off);
    if (lane == 0)
        out[b] = part + fc1b[0] * sumw + fc2b[0];
}

// ---------------------------------------------------------------------------
// Inputs (metadata order): x, h0, c0, Wih1, Whh1, bih1, bhh1, Wih2, Whh2,
//                          bih2, bhh2, fc1_w, fc1_b, fc2_w, fc2_b
// ---------------------------------------------------------------------------
extern "C" void kernel_launch(void* const* d_in, const int* in_sizes, int n_in,
                              void* d_out, int out_size)
{
    const float* x     = (const float*)d_in[0];
    const float* h0    = (const float*)d_in[1];
    const float* c0    = (const float*)d_in[2];
    const float* Wih1  = (const float*)d_in[3];
    const float* Whh1  = (const float*)d_in[4];
    const float* bih1  = (const float*)d_in[5];
    const float* bhh1  = (const float*)d_in[6];
    const float* Wih2  = (const float*)d_in[7];
    const float* Whh2  = (const float*)d_in[8];
    const float* bih2  = (const float*)d_in[9];
    const float* bhh2  = (const float*)d_in[10];
    const float* fc1w  = (const float*)d_in[11];
    const float* fc1b  = (const float*)d_in[12];
    const float* fc2w  = (const float*)d_in[13];
    const float* fc2b  = (const float*)d_in[14];
    float* out = (float*)d_out;

    xg1_kernel<<<(BB * TT) / 512, 512>>>(x, Wih1, bih1, bhh1);
    scan1_kernel<<<BB / 4, 128>>>(h0, c0, Whh1);
    xg2_kernel<<<(BB * TT) / 512, 512>>>(Wih2, bih2, bhh2);
    scan2_kernel<<<BB / 4, 128>>>(Whh2, fc1w, fc1b, fc2w, fc2b, out);
}